// round 14
// baseline (speedup 1.0000x reference)
#include <cuda_runtime.h>
#include <cstdint>
#include <math.h>

// Problem constants
#define BATCH   8192
#define NNODES  32
#define DIN     128
#define HID     128
#define TT      3

// Scratch (__device__ globals; cudaMalloc is forbidden)
__device__ float g_C[BATCH * TT * DIN];   // combined vectors (b, j*128+d)
__device__ float g_u[9 * DIN];            // u[i*3+j][d] = sum_h W[i][d][h]*a_top[j][h]
__device__ float g_v[TT * DIN];           // v[j][d]     = sum_h W[j][d][h]*a_bot[j][h]
__device__ unsigned g_det;                // mask dtype classification bits

// ---------------------------------------------------------------------------
// Mask dtype helpers (bool buffer may be u8 / i32 / f32 on device).
// ---------------------------------------------------------------------------
__device__ __forceinline__ int mask_mode_from_det(unsigned d)
{
    if (!(d & 1u)) return 1;   // int32
    if (!(d & 2u)) return 2;   // float32
    return 0;                  // uint8
}
__device__ __forceinline__ bool mask_at(const void* m, size_t idx, int mode)
{
    if (mode == 0) return ((const unsigned char*)m)[idx] != 0;
    if (mode == 1) return ((const int*)m)[idx] != 0;
    return ((const float*)m)[idx] != 0.f;
}

__device__ __forceinline__ float dot4(float4 x, float4 y)
{ return x.x * y.x + x.y * y.y + x.z * y.z + x.w * y.w; }

// ---------------------------------------------------------------------------
// k0: 8 dots per warp (MLP=8). 1536 dots -> 192 warps -> 24 blocks x 256.
// Block 24 does mask dtype detection.
// ---------------------------------------------------------------------------
__global__ __launch_bounds__(256) void k0_precompute(
    const float* __restrict__ W, const float* __restrict__ a,
    const unsigned* __restrict__ mraw)
{
    if (blockIdx.x == 24) {   // detection: scan first 8KB (2048 words)
        __shared__ unsigned sacc;
        int t = threadIdx.x;
        if (t == 0) sacc = 0u;
        __syncthreads();
        unsigned local = 0;
        for (int i = t; i < 2048; i += 256) {
            unsigned w = mraw[i];
            if (w > 1u) local |= 1u;
            if (w != 0u && w != 0x3F800000u) local |= 2u;
        }
        if (local) atomicOr(&sacc, local);
        __syncthreads();
        if (t == 0) g_det = sacc;
        return;
    }
    const int lane = threadIdx.x & 31;
    const int wg   = blockIdx.x * 8 + (threadIdx.x >> 5);   // 0..191
    const int base = wg * 8;                                // dot ids base..base+7
    const int vb   = base >> 7;                             // 0..11 (const across 8)
    const int d0   = base & 127;

    const float* Wbase;
    const float* avec;
    if (vb < 9) {
        Wbase = W + (size_t)(vb / 3) * (DIN * HID);
        avec  = a + (vb % 3) * (2 * HID);
    } else {
        Wbase = W + (size_t)(vb - 9) * (DIN * HID);
        avec  = a + (vb - 9) * (2 * HID) + HID;
    }
    float4 av = *(const float4*)&avec[lane << 2];

    float acc[8];
    #pragma unroll
    for (int r = 0; r < 8; ++r) {
        float4 wv = *(const float4*)&Wbase[(size_t)(d0 + r) * HID + (lane << 2)];
        acc[r] = dot4(wv, av);
    }
    #pragma unroll
    for (int o = 16; o; o >>= 1)
        #pragma unroll
        for (int r = 0; r < 8; ++r)
            acc[r] += __shfl_xor_sync(0xffffffffu, acc[r], o);
    if (lane == 0) {
        float4 lo = {acc[0], acc[1], acc[2], acc[3]};
        float4 hi = {acc[4], acc[5], acc[6], acc[7]};
        if (vb < 9) {
            *(float4*)&g_u[vb * DIN + d0]     = lo;
            *(float4*)&g_u[vb * DIN + d0 + 4] = hi;
        } else {
            *(float4*)&g_v[(vb - 9) * DIN + d0]     = lo;
            *(float4*)&g_v[(vb - 9) * DIN + d0 + 4] = hi;
        }
    }
}

// ---------------------------------------------------------------------------
// k1-lite (round-9 body, occupancy 3 -> 4): one WARP per batch.
// ---------------------------------------------------------------------------
#define K1_WARPS 8
#define WSL      224   // per-warp smem floats: nb[3][32] + ss[16] + wt[3][32] + pad

__global__ __launch_bounds__(256, 4) void k1_scores_combine(
    const float* __restrict__ h, const void* __restrict__ mask)
{
    __shared__ float smem[K1_WARPS * WSL];
    const int lane = threadIdx.x & 31;
    const int w    = threadIdx.x >> 5;
    const int b    = blockIdx.x * K1_WARPS + w;
    const int mode = mask_mode_from_det(g_det);
    float* snb = smem + w * WSL;     // [3][32] neighbor scores
    float* sss = snb + 96;           // [9] self scores (+pad)
    float* swt = sss + 16;           // [3][32] weights

    const int g = lane >> 3;         // group 0..3 (node within 4-pack)
    const int q = lane & 7;          // quarter position 0..7

    const float* hb = h + (size_t)b * NNODES * DIN;

    // ---- masks early (hide latency under dot phase) ----
    const size_t mstr = (size_t)BATCH * NNODES;
    const size_t mb   = (size_t)b * NNODES + lane;
    const bool m0 = mask_at(mask, 0 * mstr + mb, mode);
    const bool m1 = mask_at(mask, 1 * mstr + mb, mode);
    const bool m2 = mask_at(mask, 2 * mstr + mb, mode);

    // ---- dot phase: 8 iterations x 4 nodes ----
    #pragma unroll
    for (int it = 0; it < 8; ++it) {
        const int node = (it << 2) + g;
        const float4* rowp = (const float4*)(hb + node * DIN);
        float p0 = 0.f, p1 = 0.f, p2 = 0.f;
        #pragma unroll
        for (int k = 0; k < 4; ++k) {
            float4 x  = rowp[q + (k << 3)];
            float4 v0 = *(const float4*)&g_v[0 * DIN + ((q + (k << 3)) << 2)];
            float4 v1 = *(const float4*)&g_v[1 * DIN + ((q + (k << 3)) << 2)];
            float4 v2 = *(const float4*)&g_v[2 * DIN + ((q + (k << 3)) << 2)];
            p0 += dot4(x, v0); p1 += dot4(x, v1); p2 += dot4(x, v2);
        }
        #pragma unroll
        for (int o = 4; o; o >>= 1) {
            p0 += __shfl_xor_sync(0xffffffffu, p0, o);
            p1 += __shfl_xor_sync(0xffffffffu, p1, o);
            p2 += __shfl_xor_sync(0xffffffffu, p2, o);
        }
        if (q == 0) {
            snb[0 * 32 + node] = p0;
            snb[1 * 32 + node] = p1;
            snb[2 * 32 + node] = p2;
        }
    }

    // ---- s_self: 9 u-dots on node-0 row (warp-uniform loop shape) ----
    {
        float4 x0[4];
        #pragma unroll
        for (int k = 0; k < 4; ++k)
            x0[k] = ((const float4*)hb)[q + (k << 3)];   // node-0 row
        #pragma unroll
        for (int t = 0; t < 3; ++t) {
            int ui = g * 3 + t; if (ui > 8) ui = 8;      // groups 2/3 dup ui=8 (benign)
            const float* uvec = g_u + ui * DIN;
            float p = 0.f;
            #pragma unroll
            for (int k = 0; k < 4; ++k)
                p += dot4(x0[k], *(const float4*)&uvec[(q + (k << 3)) << 2]);
            #pragma unroll
            for (int o = 4; o; o >>= 1) p += __shfl_xor_sync(0xffffffffu, p, o);
            if (q == 0) sss[ui] = p;
        }
    }
    __syncwarp();

    // ---- dual register-resident softmax (lanes 1..15 ally, 16..31 opp) ----
    const float r0 = snb[0 * 32 + lane];
    const float r1 = snb[1 * 32 + lane];
    const float r2 = snb[2 * 32 + lane];
    float ss[9];
    #pragma unroll
    for (int k = 0; k < 9; ++k) ss[k] = sss[k];

    const float eb0 = (m0 || lane == 0) ? -INFINITY : r0;
    const float eb1 = (m1 || lane == 0) ? -INFINITY : r1;
    const float eb2 = (m2 || lane == 0) ? -INFINITY : r2;

    float mx = -INFINITY;
    #pragma unroll
    for (int i = 0; i < 3; ++i) {
        mx = fmaxf(mx, ss[i * 3 + 0] + eb0);
        mx = fmaxf(mx, ss[i * 3 + 1] + eb1);
        mx = fmaxf(mx, ss[i * 3 + 2] + eb2);
    }
    #pragma unroll
    for (int o = 8; o; o >>= 1) mx = fmaxf(mx, __shfl_xor_sync(0xffffffffu, mx, o));

    float s0 = 0.f, s1 = 0.f, s2 = 0.f;
    #pragma unroll
    for (int i = 0; i < 3; ++i) {
        s0 += __expf(ss[i * 3 + 0] + eb0 - mx);
        s1 += __expf(ss[i * 3 + 1] + eb1 - mx);
        s2 += __expf(ss[i * 3 + 2] + eb2 - mx);
    }
    float zs = s0 + s1 + s2;
    #pragma unroll
    for (int o = 8; o; o >>= 1) zs += __shfl_xor_sync(0xffffffffu, zs, o);
    // all-masked half -> zs NaN -> inv 0 -> weights 0 (matches reference)
    const float inv = (zs > 0.f) ? (1.f / zs) : 0.f;

    swt[0 * 32 + lane] = (lane == 0) ? (m0 ? 1.f : 0.f) : s0 * inv;
    swt[1 * 32 + lane] = (lane == 0) ? (m1 ? 1.f : 0.f) : s1 * inv;
    swt[2 * 32 + lane] = (lane == 0) ? (m2 ? 1.f : 0.f) : s2 * inv;
    __syncwarp();

    // ---- combine: re-read h (L1/L2 hot), coalesced, FMA into 3 accs ----
    const float4* hv = (const float4*)hb;
    float4 a0 = {0.f, 0.f, 0.f, 0.f}, a1 = a0, a2 = a0;
    #pragma unroll
    for (int n = 0; n < NNODES; ++n) {
        float4 x = hv[(n << 5) + lane];
        float w0 = swt[n], w1 = swt[32 + n], w2 = swt[64 + n];
        a0.x += w0 * x.x; a0.y += w0 * x.y; a0.z += w0 * x.z; a0.w += w0 * x.w;
        a1.x += w1 * x.x; a1.y += w1 * x.y; a1.z += w1 * x.z; a1.w += w1 * x.w;
        a2.x += w2 * x.x; a2.y += w2 * x.y; a2.z += w2 * x.z; a2.w += w2 * x.w;
    }
    float* gout = g_C + (size_t)b * (TT * DIN);
    const int d4 = lane << 2;
    *(float4*)&gout[0 * DIN + d4] = a0;
    *(float4*)&gout[1 * DIN + d4] = a1;
    *(float4*)&gout[2 * DIN + d4] = a2;
}

// ---------------------------------------------------------------------------
// k2 v4: out = elu(C @ Wstack). M=8192, K=384, N=128. fp32 packed FFMA2.
// BM=128, BN=32, BK=64; block=256; grid=(64,4)=256 CTAs (~14 warps/SM, same
// as r9 but 2x ILP: per-thread 4(M)x4(N) = 32 FMA2 per 4-k-step).
// A row-major smem: 1 LDS.128 = 4 k-values; B = 1 broadcast LDS.128 per k.
// ---------------------------------------------------------------------------
#define GBM 128
#define GBN 32
#define GBK 64
#define AST (GBK + 4)   // As row stride 68 floats -> LDS.128 conflict-free

#define FMA_F32X2(d, a, bb, c) \
    asm("fma.rn.f32x2 %0, %1, %2, %3;" : "=l"(d) : "l"(a), "l"(bb), "l"(c))
#define PACK_DUP(d, s) \
    asm("mov.b64 %0, {%1, %1};" : "=l"(d) : "r"(s))

__global__ __launch_bounds__(256) void k2_gemm_elu(
    const float* __restrict__ W, float* __restrict__ out)
{
    __shared__ float As[GBM][AST];   // [m][k] row-major, 34.8 KB
    __shared__ float Bs[GBK][GBN];   // [k][n], 8 KB

    const int tid = threadIdx.x;
    const int bm0 = blockIdx.x * GBM;
    const int bn0 = blockIdx.y * GBN;
    const int tm0 = tid & 31;               // m = tm0 + 32*mi, mi 0..3
    const int tn  = (tid >> 5) << 2;        // warp-uniform, 0..28

    unsigned long long acc[4][2];           // [mi][n-pair]
    #pragma unroll
    for (int i = 0; i < 4; ++i) { acc[i][0] = 0ull; acc[i][1] = 0ull; }

    const float* A = g_C;

    for (int k0 = 0; k0 < TT * DIN; k0 += GBK) {
        // A tile 128x64: straight row-major copy, 8 float4 per thread
        #pragma unroll
        for (int i = 0; i < 8; ++i) {
            int li = tid + i * 256;
            int r  = li >> 4;                // m row 0..127
            int c4 = (li & 15) << 2;         // k col 0..60
            *(float4*)&As[r][c4] =
                *(const float4*)&A[(size_t)(bm0 + r) * (TT * DIN) + k0 + c4];
        }
        // B tile 64x32: 2 float4 per thread
        #pragma unroll
        for (int i = 0; i < 2; ++i) {
            int li = tid + i * 256;
            int r  = li >> 3;                // k row 0..63
            int c4 = (li & 7) << 2;          // n col 0..28
            *(float4*)&Bs[r][c4] = *(const float4*)&W[(size_t)(k0 + r) * DIN + bn0 + c4];
        }
        __syncthreads();

        #pragma unroll
        for (int kb = 0; kb < GBK; kb += 4) {
            float av[4][4];
            #pragma unroll
            for (int mi = 0; mi < 4; ++mi)
                *(float4*)av[mi] = *(const float4*)&As[tm0 + 32 * mi][kb];
            #pragma unroll
            for (int kk = 0; kk < 4; ++kk) {
                ulonglong2 bb = *(const ulonglong2*)&Bs[kb + kk][tn];  // broadcast
                #pragma unroll
                for (int mi = 0; mi < 4; ++mi) {
                    unsigned long long ad;
                    PACK_DUP(ad, __float_as_uint(av[mi][kk]));
                    FMA_F32X2(acc[mi][0], ad, bb.x, acc[mi][0]);
                    FMA_F32X2(acc[mi][1], ad, bb.y, acc[mi][1]);
                }
            }
        }
        __syncthreads();
    }

    // epilogue: unpack, ELU, store
    #pragma unroll
    for (int mi = 0; mi < 4; ++mi) {
        int m = bm0 + tm0 + 32 * mi;
        float o4[4];
        #pragma unroll
        for (int jj = 0; jj < 2; ++jj) {
            unsigned long long p = acc[mi][jj];
            o4[2 * jj]     = __uint_as_float((unsigned)(p & 0xffffffffull));
            o4[2 * jj + 1] = __uint_as_float((unsigned)(p >> 32));
        }
        #pragma unroll
        for (int q = 0; q < 4; ++q) {
            float x = o4[q];
            o4[q] = x > 0.f ? x : expm1f(x);
        }
        *(float4*)&out[(size_t)m * DIN + bn0 + tn] = *(float4*)&o4[0];
    }
}

// ---------------------------------------------------------------------------
extern "C" void kernel_launch(void* const* d_in, const int* in_sizes, int n_in,
                              void* d_out, int out_size)
{
    const float* h = nullptr;
    const void*  mask = nullptr;
    const float* W = nullptr;
    const float* a = nullptr;

    for (int i = 0; i < n_in; ++i) {
        switch (in_sizes[i]) {
            case BATCH * NNODES * DIN: h    = (const float*)d_in[i]; break;   // 33554432
            case TT * BATCH * NNODES:  mask = d_in[i];               break;   // 786432
            case TT * DIN * HID:       W    = (const float*)d_in[i]; break;   // 49152
            case TT * 2 * HID:         a    = (const float*)d_in[i]; break;   // 768
            default: break; // scalars
        }
    }

    k0_precompute<<<25, 256>>>(W, a, (const unsigned*)mask);
    k1_scores_combine<<<BATCH / K1_WARPS, 32 * K1_WARPS>>>(h, mask);
    k2_gemm_elu<<<dim3(BATCH / GBM, DIN / GBN), 256>>>(W, (float*)d_out);
}

// round 15
// speedup vs baseline: 1.0780x; 1.0780x over previous
#include <cuda_runtime.h>
#include <cstdint>
#include <math.h>

// Problem constants
#define BATCH   8192
#define NNODES  32
#define DIN     128
#define HID     128
#define TT      3

// Scratch (__device__ globals; cudaMalloc is forbidden)
__device__ float g_u[9 * DIN];            // u[i*3+j][d] = sum_h W[i][d][h]*a_top[j][h]
__device__ float g_v[TT * DIN];           // v[j][d]     = sum_h W[j][d][h]*a_bot[j][h]
__device__ unsigned g_det;                // mask dtype classification bits

// ---------------------------------------------------------------------------
// Mask dtype helpers (bool buffer may be u8 / i32 / f32 on device).
// ---------------------------------------------------------------------------
__device__ __forceinline__ int mask_mode_from_det(unsigned d)
{
    if (!(d & 1u)) return 1;   // int32
    if (!(d & 2u)) return 2;   // float32
    return 0;                  // uint8
}
__device__ __forceinline__ bool mask_at(const void* m, size_t idx, int mode)
{
    if (mode == 0) return ((const unsigned char*)m)[idx] != 0;
    if (mode == 1) return ((const int*)m)[idx] != 0;
    return ((const float*)m)[idx] != 0.f;
}

__device__ __forceinline__ float dot4(float4 x, float4 y)
{ return x.x * y.x + x.y * y.y + x.z * y.z + x.w * y.w; }

#define FMA_F32X2(d, a, bb, c) \
    asm("fma.rn.f32x2 %0, %1, %2, %3;" : "=l"(d) : "l"(a), "l"(bb), "l"(c))
#define PACK_DUP(d, s) \
    asm("mov.b64 %0, {%1, %1};" : "=l"(d) : "r"(s))

// ---------------------------------------------------------------------------
// k0: 8 dots per warp. 1536 dots -> 192 warps -> 24 blocks x 256.
// Block 24 does mask dtype detection.
// ---------------------------------------------------------------------------
__global__ __launch_bounds__(256) void k0_precompute(
    const float* __restrict__ W, const float* __restrict__ a,
    const unsigned* __restrict__ mraw)
{
    if (blockIdx.x == 24) {   // detection: scan first 8KB (2048 words)
        __shared__ unsigned sacc;
        int t = threadIdx.x;
        if (t == 0) sacc = 0u;
        __syncthreads();
        unsigned local = 0;
        for (int i = t; i < 2048; i += 256) {
            unsigned w = mraw[i];
            if (w > 1u) local |= 1u;
            if (w != 0u && w != 0x3F800000u) local |= 2u;
        }
        if (local) atomicOr(&sacc, local);
        __syncthreads();
        if (t == 0) g_det = sacc;
        return;
    }
    const int lane = threadIdx.x & 31;
    const int wg   = blockIdx.x * 8 + (threadIdx.x >> 5);   // 0..191
    const int base = wg * 8;                                // dot ids base..base+7
    const int vb   = base >> 7;                             // 0..11 (const across 8)
    const int d0   = base & 127;

    const float* Wbase;
    const float* avec;
    if (vb < 9) {
        Wbase = W + (size_t)(vb / 3) * (DIN * HID);
        avec  = a + (vb % 3) * (2 * HID);
    } else {
        Wbase = W + (size_t)(vb - 9) * (DIN * HID);
        avec  = a + (vb - 9) * (2 * HID) + HID;
    }
    float4 av = *(const float4*)&avec[lane << 2];

    float acc[8];
    #pragma unroll
    for (int r = 0; r < 8; ++r) {
        float4 wv = *(const float4*)&Wbase[(size_t)(d0 + r) * HID + (lane << 2)];
        acc[r] = dot4(wv, av);
    }
    #pragma unroll
    for (int o = 16; o; o >>= 1)
        #pragma unroll
        for (int r = 0; r < 8; ++r)
            acc[r] += __shfl_xor_sync(0xffffffffu, acc[r], o);
    if (lane == 0) {
        float4 lo = {acc[0], acc[1], acc[2], acc[3]};
        float4 hi = {acc[4], acc[5], acc[6], acc[7]};
        if (vb < 9) {
            *(float4*)&g_u[vb * DIN + d0]     = lo;
            *(float4*)&g_u[vb * DIN + d0 + 4] = hi;
        } else {
            *(float4*)&g_v[(vb - 9) * DIN + d0]     = lo;
            *(float4*)&g_v[(vb - 9) * DIN + d0 + 4] = hi;
        }
    }
}

// ---------------------------------------------------------------------------
// k1 (fully fused): warp-per-batch scores+softmax+combine (round-9 proven),
// then CTA-level mini-GEMM out = elu(c @ Wstack) with W read ONCE per CTA
// and reused across 4 batches in registers.
// 8 warps/CTA, grid=1024, __launch_bounds__(256,3).
// ---------------------------------------------------------------------------
#define K1_WARPS 8
#define WSL   224                 // per-warp: nb[3][32] + ss[16] + wt[3][32] + pad
#define AROW  388                 // A row stride (384 + pad)

__global__ __launch_bounds__(256, 3) void k1_fused(
    const float* __restrict__ h, const void* __restrict__ mask,
    const float* __restrict__ W, float* __restrict__ out)
{
    __shared__ float smem[K1_WARPS * WSL];        // 7.2 KB scores/weights
    __shared__ float Amat[K1_WARPS][AROW];        // 12.4 KB c-vectors (8 x 384)
    __shared__ float Pmat[4][K1_WARPS][DIN];      // 16 KB k-group partials

    const int lane = threadIdx.x & 31;
    const int w    = threadIdx.x >> 5;
    const int b    = blockIdx.x * K1_WARPS + w;
    const int mode = mask_mode_from_det(g_det);
    float* snb = smem + w * WSL;     // [3][32] neighbor scores
    float* sss = snb + 96;           // [9] self scores (+pad)
    float* swt = sss + 16;           // [3][32] weights

    const int g = lane >> 3;         // group 0..3 (node within 4-pack)
    const int q = lane & 7;          // quarter position 0..7

    const float* hb = h + (size_t)b * NNODES * DIN;

    // ---- masks early (hide latency under dot phase) ----
    const size_t mstr = (size_t)BATCH * NNODES;
    const size_t mb   = (size_t)b * NNODES + lane;
    const bool m0 = mask_at(mask, 0 * mstr + mb, mode);
    const bool m1 = mask_at(mask, 1 * mstr + mb, mode);
    const bool m2 = mask_at(mask, 2 * mstr + mb, mode);

    // ---- dot phase: 8 iterations x 4 nodes ----
    #pragma unroll
    for (int it = 0; it < 8; ++it) {
        const int node = (it << 2) + g;
        const float4* rowp = (const float4*)(hb + node * DIN);
        float p0 = 0.f, p1 = 0.f, p2 = 0.f;
        #pragma unroll
        for (int k = 0; k < 4; ++k) {
            float4 x  = rowp[q + (k << 3)];
            float4 v0 = *(const float4*)&g_v[0 * DIN + ((q + (k << 3)) << 2)];
            float4 v1 = *(const float4*)&g_v[1 * DIN + ((q + (k << 3)) << 2)];
            float4 v2 = *(const float4*)&g_v[2 * DIN + ((q + (k << 3)) << 2)];
            p0 += dot4(x, v0); p1 += dot4(x, v1); p2 += dot4(x, v2);
        }
        #pragma unroll
        for (int o = 4; o; o >>= 1) {
            p0 += __shfl_xor_sync(0xffffffffu, p0, o);
            p1 += __shfl_xor_sync(0xffffffffu, p1, o);
            p2 += __shfl_xor_sync(0xffffffffu, p2, o);
        }
        if (q == 0) {
            snb[0 * 32 + node] = p0;
            snb[1 * 32 + node] = p1;
            snb[2 * 32 + node] = p2;
        }
    }

    // ---- s_self: 9 u-dots on node-0 row (warp-uniform loop shape) ----
    {
        float4 x0[4];
        #pragma unroll
        for (int k = 0; k < 4; ++k)
            x0[k] = ((const float4*)hb)[q + (k << 3)];   // node-0 row
        #pragma unroll
        for (int t = 0; t < 3; ++t) {
            int ui = g * 3 + t; if (ui > 8) ui = 8;      // groups 2/3 dup ui=8 (benign)
            const float* uvec = g_u + ui * DIN;
            float p = 0.f;
            #pragma unroll
            for (int k = 0; k < 4; ++k)
                p += dot4(x0[k], *(const float4*)&uvec[(q + (k << 3)) << 2]);
            #pragma unroll
            for (int o = 4; o; o >>= 1) p += __shfl_xor_sync(0xffffffffu, p, o);
            if (q == 0) sss[ui] = p;
        }
    }
    __syncwarp();

    // ---- dual register-resident softmax (lanes 1..15 ally, 16..31 opp) ----
    const float r0 = snb[0 * 32 + lane];
    const float r1 = snb[1 * 32 + lane];
    const float r2 = snb[2 * 32 + lane];
    float ss[9];
    #pragma unroll
    for (int k = 0; k < 9; ++k) ss[k] = sss[k];

    const float eb0 = (m0 || lane == 0) ? -INFINITY : r0;
    const float eb1 = (m1 || lane == 0) ? -INFINITY : r1;
    const float eb2 = (m2 || lane == 0) ? -INFINITY : r2;

    float mx = -INFINITY;
    #pragma unroll
    for (int i = 0; i < 3; ++i) {
        mx = fmaxf(mx, ss[i * 3 + 0] + eb0);
        mx = fmaxf(mx, ss[i * 3 + 1] + eb1);
        mx = fmaxf(mx, ss[i * 3 + 2] + eb2);
    }
    #pragma unroll
    for (int o = 8; o; o >>= 1) mx = fmaxf(mx, __shfl_xor_sync(0xffffffffu, mx, o));

    float s0 = 0.f, s1 = 0.f, s2 = 0.f;
    #pragma unroll
    for (int i = 0; i < 3; ++i) {
        s0 += __expf(ss[i * 3 + 0] + eb0 - mx);
        s1 += __expf(ss[i * 3 + 1] + eb1 - mx);
        s2 += __expf(ss[i * 3 + 2] + eb2 - mx);
    }
    float zs = s0 + s1 + s2;
    #pragma unroll
    for (int o = 8; o; o >>= 1) zs += __shfl_xor_sync(0xffffffffu, zs, o);
    // all-masked half -> zs NaN -> inv 0 -> weights 0 (matches reference)
    const float inv = (zs > 0.f) ? (1.f / zs) : 0.f;

    swt[0 * 32 + lane] = (lane == 0) ? (m0 ? 1.f : 0.f) : s0 * inv;
    swt[1 * 32 + lane] = (lane == 0) ? (m1 ? 1.f : 0.f) : s1 * inv;
    swt[2 * 32 + lane] = (lane == 0) ? (m2 ? 1.f : 0.f) : s2 * inv;
    __syncwarp();

    // ---- combine: re-read h (L1/L2 hot), write c into smem A[w][.] ----
    {
        const float4* hv = (const float4*)hb;
        float4 a0 = {0.f, 0.f, 0.f, 0.f}, a1 = a0, a2 = a0;
        #pragma unroll
        for (int n = 0; n < NNODES; ++n) {
            float4 x = hv[(n << 5) + lane];
            float w0 = swt[n], w1 = swt[32 + n], w2 = swt[64 + n];
            a0.x += w0 * x.x; a0.y += w0 * x.y; a0.z += w0 * x.z; a0.w += w0 * x.w;
            a1.x += w1 * x.x; a1.y += w1 * x.y; a1.z += w1 * x.z; a1.w += w1 * x.w;
            a2.x += w2 * x.x; a2.y += w2 * x.y; a2.z += w2 * x.z; a2.w += w2 * x.w;
        }
        const int d4 = lane << 2;
        *(float4*)&Amat[w][0 * DIN + d4] = a0;
        *(float4*)&Amat[w][1 * DIN + d4] = a1;
        *(float4*)&Amat[w][2 * DIN + d4] = a2;
    }
    __syncthreads();

    // ---- mini-GEMM: out[b][d] = sum_k A[b][k] * Wstack[k][d] ----
    // warp = (bg = w&1: 4 batches) x (kg = w>>1: 96 k-values).
    // Lane owns d-quad; each 16B W-load feeds 4 batches (8 FMA2).
    {
        const int bg = w & 1;
        const int kg = w >> 1;
        const int d0 = lane << 2;
        const int kbase = kg * 96;

        unsigned long long acc[4][2];
        #pragma unroll
        for (int bi = 0; bi < 4; ++bi) { acc[bi][0] = 0ull; acc[bi][1] = 0ull; }

        const float* arow0 = &Amat[bg * 4 + 0][kbase];
        const float* arow1 = &Amat[bg * 4 + 1][kbase];
        const float* arow2 = &Amat[bg * 4 + 2][kbase];
        const float* arow3 = &Amat[bg * 4 + 3][kbase];

        #pragma unroll 4
        for (int kk = 0; kk < 96; ++kk) {
            ulonglong2 wrow = *(const ulonglong2*)&W[(size_t)(kbase + kk) * DIN + d0];
            unsigned long long ad;
            PACK_DUP(ad, __float_as_uint(arow0[kk]));
            FMA_F32X2(acc[0][0], ad, wrow.x, acc[0][0]);
            FMA_F32X2(acc[0][1], ad, wrow.y, acc[0][1]);
            PACK_DUP(ad, __float_as_uint(arow1[kk]));
            FMA_F32X2(acc[1][0], ad, wrow.x, acc[1][0]);
            FMA_F32X2(acc[1][1], ad, wrow.y, acc[1][1]);
            PACK_DUP(ad, __float_as_uint(arow2[kk]));
            FMA_F32X2(acc[2][0], ad, wrow.x, acc[2][0]);
            FMA_F32X2(acc[2][1], ad, wrow.y, acc[2][1]);
            PACK_DUP(ad, __float_as_uint(arow3[kk]));
            FMA_F32X2(acc[3][0], ad, wrow.x, acc[3][0]);
            FMA_F32X2(acc[3][1], ad, wrow.y, acc[3][1]);
        }

        #pragma unroll
        for (int bi = 0; bi < 4; ++bi) {
            float4 pv;
            pv.x = __uint_as_float((unsigned)(acc[bi][0] & 0xffffffffull));
            pv.y = __uint_as_float((unsigned)(acc[bi][0] >> 32));
            pv.z = __uint_as_float((unsigned)(acc[bi][1] & 0xffffffffull));
            pv.w = __uint_as_float((unsigned)(acc[bi][1] >> 32));
            *(float4*)&Pmat[kg][bg * 4 + bi][d0] = pv;
        }
    }
    __syncthreads();

    // ---- reduce 4 k-group partials, ELU, store ----
    {
        const int tid = threadIdx.x;
        const int bl  = tid >> 5;            // batch-local 0..7
        const int d0  = (tid & 31) << 2;
        float4 p0 = *(const float4*)&Pmat[0][bl][d0];
        float4 p1 = *(const float4*)&Pmat[1][bl][d0];
        float4 p2 = *(const float4*)&Pmat[2][bl][d0];
        float4 p3 = *(const float4*)&Pmat[3][bl][d0];
        float o4[4];
        o4[0] = (p0.x + p1.x) + (p2.x + p3.x);
        o4[1] = (p0.y + p1.y) + (p2.y + p3.y);
        o4[2] = (p0.z + p1.z) + (p2.z + p3.z);
        o4[3] = (p0.w + p1.w) + (p2.w + p3.w);
        #pragma unroll
        for (int qq = 0; qq < 4; ++qq) {
            float x = o4[qq];
            o4[qq] = x > 0.f ? x : expm1f(x);
        }
        const size_t ob = (size_t)(blockIdx.x * K1_WARPS + bl) * DIN + d0;
        *(float4*)&out[ob] = *(float4*)&o4[0];
    }
}

// ---------------------------------------------------------------------------
extern "C" void kernel_launch(void* const* d_in, const int* in_sizes, int n_in,
                              void* d_out, int out_size)
{
    const float* h = nullptr;
    const void*  mask = nullptr;
    const float* W = nullptr;
    const float* a = nullptr;

    for (int i = 0; i < n_in; ++i) {
        switch (in_sizes[i]) {
            case BATCH * NNODES * DIN: h    = (const float*)d_in[i]; break;   // 33554432
            case TT * BATCH * NNODES:  mask = d_in[i];               break;   // 786432
            case TT * DIN * HID:       W    = (const float*)d_in[i]; break;   // 49152
            case TT * 2 * HID:         a    = (const float*)d_in[i]; break;   // 768
            default: break; // scalars
        }
    }

    k0_precompute<<<25, 256>>>(W, a, (const unsigned*)mask);
    k1_fused<<<BATCH / K1_WARPS, 32 * K1_WARPS>>>(h, mask, W, (float*)d_out);
}

// round 17
// speedup vs baseline: 1.1771x; 1.0919x over previous
#include <cuda_runtime.h>
#include <cstdint>
#include <math.h>

// Problem constants
#define BATCH   8192
#define NNODES  32
#define DIN     128
#define HID     128
#define TT      3

// Scratch (__device__ globals; cudaMalloc is forbidden)
__device__ float g_u[9 * DIN];            // u[i*3+j][d] = sum_h W[i][d][h]*a_top[j][h]
__device__ float g_v[TT * DIN];           // v[j][d]     = sum_h W[j][d][h]*a_bot[j][h]
__device__ unsigned g_det;                // mask dtype classification bits

// ---------------------------------------------------------------------------
// Mask dtype helpers (bool buffer may be u8 / i32 / f32 on device).
// ---------------------------------------------------------------------------
__device__ __forceinline__ int mask_mode_from_det(unsigned d)
{
    if (!(d & 1u)) return 1;   // int32
    if (!(d & 2u)) return 2;   // float32
    return 0;                  // uint8
}
__device__ __forceinline__ bool mask_at(const void* m, size_t idx, int mode)
{
    if (mode == 0) return ((const unsigned char*)m)[idx] != 0;
    if (mode == 1) return ((const int*)m)[idx] != 0;
    return ((const float*)m)[idx] != 0.f;
}

__device__ __forceinline__ float dot4(float4 x, float4 y)
{ return x.x * y.x + x.y * y.y + x.z * y.z + x.w * y.w; }

#define FMA_F32X2(d, a, bb, c) \
    asm("fma.rn.f32x2 %0, %1, %2, %3;" : "=l"(d) : "l"(a), "l"(bb), "l"(c))
#define PACK_DUP(d, s) \
    asm("mov.b64 %0, {%1, %1};" : "=l"(d) : "r"(s))

// ---------------------------------------------------------------------------
// k0: 8 dots per warp. 1536 dots -> 192 warps -> 24 blocks x 256.
// Block 24 does mask dtype detection.
// ---------------------------------------------------------------------------
__global__ __launch_bounds__(256) void k0_precompute(
    const float* __restrict__ W, const float* __restrict__ a,
    const unsigned* __restrict__ mraw)
{
    if (blockIdx.x == 24) {   // detection: scan first 8KB (2048 words)
        __shared__ unsigned sacc;
        int t = threadIdx.x;
        if (t == 0) sacc = 0u;
        __syncthreads();
        unsigned local = 0;
        for (int i = t; i < 2048; i += 256) {
            unsigned w = mraw[i];
            if (w > 1u) local |= 1u;
            if (w != 0u && w != 0x3F800000u) local |= 2u;
        }
        if (local) atomicOr(&sacc, local);
        __syncthreads();
        if (t == 0) g_det = sacc;
        return;
    }
    const int lane = threadIdx.x & 31;
    const int wg   = blockIdx.x * 8 + (threadIdx.x >> 5);   // 0..191
    const int base = wg * 8;                                // dot ids base..base+7
    const int vb   = base >> 7;                             // 0..11 (const across 8)
    const int d0   = base & 127;

    const float* Wbase;
    const float* avec;
    if (vb < 9) {
        Wbase = W + (size_t)(vb / 3) * (DIN * HID);
        avec  = a + (vb % 3) * (2 * HID);
    } else {
        Wbase = W + (size_t)(vb - 9) * (DIN * HID);
        avec  = a + (vb - 9) * (2 * HID) + HID;
    }
    float4 av = *(const float4*)&avec[lane << 2];

    float acc[8];
    #pragma unroll
    for (int r = 0; r < 8; ++r) {
        float4 wv = *(const float4*)&Wbase[(size_t)(d0 + r) * HID + (lane << 2)];
        acc[r] = dot4(wv, av);
    }
    #pragma unroll
    for (int o = 16; o; o >>= 1)
        #pragma unroll
        for (int r = 0; r < 8; ++r)
            acc[r] += __shfl_xor_sync(0xffffffffu, acc[r], o);
    if (lane == 0) {
        float4 lo = {acc[0], acc[1], acc[2], acc[3]};
        float4 hi = {acc[4], acc[5], acc[6], acc[7]};
        if (vb < 9) {
            *(float4*)&g_u[vb * DIN + d0]     = lo;
            *(float4*)&g_u[vb * DIN + d0 + 4] = hi;
        } else {
            *(float4*)&g_v[(vb - 9) * DIN + d0]     = lo;
            *(float4*)&g_v[(vb - 9) * DIN + d0 + 4] = hi;
        }
    }
}

// ---------------------------------------------------------------------------
// k1 (fully fused, v/u staged in smem to free ~48 regs -> 4 CTAs/SM):
// warp-per-batch scores+softmax+combine, then CTA-level mini-GEMM with
// W read once per CTA and reused across 4 batches in registers.
// 8 warps/CTA, grid=1024, __launch_bounds__(256,4).
// ---------------------------------------------------------------------------
#define K1_WARPS 8
#define WSL   224                 // per-warp: nb[3][32] + ss[16] + wt[3][32] + pad
#define AROW  388                 // A row stride (384 + pad)

__global__ __launch_bounds__(256, 4) void k1_fused(
    const float* __restrict__ h, const void* __restrict__ mask,
    const float* __restrict__ W, float* __restrict__ out)
{
    __shared__ float smem[K1_WARPS * WSL];        // 7.2 KB scores/weights
    __shared__ float Amat[K1_WARPS][AROW];        // 12.4 KB c-vectors (8 x 384)
    __shared__ float Pmat[4][K1_WARPS][DIN];      // 16 KB k-group partials
    __shared__ float suv[12 * DIN];               // 6 KB: v[0..2] then u[0..8]

    const int lane = threadIdx.x & 31;
    const int w    = threadIdx.x >> 5;
    const int b    = blockIdx.x * K1_WARPS + w;
    const int mode = mask_mode_from_det(g_det);
    float* snb = smem + w * WSL;     // [3][32] neighbor scores
    float* sss = snb + 96;           // [9] self scores (+pad)
    float* swt = sss + 16;           // [3][32] weights

    const int g = lane >> 3;         // group 0..3 (node within 4-pack)
    const int q = lane & 7;          // quarter position 0..7

    const float* hb = h + (size_t)b * NNODES * DIN;

    // ---- stage v (3x128 = 96 float4) and u (9x128 = 288 float4) ----
    // FIX (r16 bug): 384 float4 > 256 threads -> MUST grid-stride the copy.
    for (int t = threadIdx.x; t < 384; t += 256) {
        if (t < 96) ((float4*)suv)[t] = ((const float4*)g_v)[t];
        else        ((float4*)(suv + TT * DIN))[t - 96] = ((const float4*)g_u)[t - 96];
    }

    // ---- masks early (hide latency under staging/dot phase) ----
    const size_t mstr = (size_t)BATCH * NNODES;
    const size_t mb   = (size_t)b * NNODES + lane;
    const bool m0 = mask_at(mask, 0 * mstr + mb, mode);
    const bool m1 = mask_at(mask, 1 * mstr + mb, mode);
    const bool m2 = mask_at(mask, 2 * mstr + mb, mode);
    __syncthreads();   // suv visible to all warps

    const float* sv0 = suv;                  // v[0]
    const float* sv1 = suv + DIN;            // v[1]
    const float* sv2 = suv + 2 * DIN;        // v[2]
    const float* suu = suv + 3 * DIN;        // u[0..8]

    // ---- dot phase: 8 iterations x 4 nodes (v reads = broadcast LDS) ----
    #pragma unroll
    for (int it = 0; it < 8; ++it) {
        const int node = (it << 2) + g;
        const float4* rowp = (const float4*)(hb + node * DIN);
        float p0 = 0.f, p1 = 0.f, p2 = 0.f;
        #pragma unroll
        for (int k = 0; k < 4; ++k) {
            float4 x  = rowp[q + (k << 3)];
            float4 v0 = *(const float4*)&sv0[(q + (k << 3)) << 2];
            float4 v1 = *(const float4*)&sv1[(q + (k << 3)) << 2];
            float4 v2 = *(const float4*)&sv2[(q + (k << 3)) << 2];
            p0 += dot4(x, v0); p1 += dot4(x, v1); p2 += dot4(x, v2);
        }
        #pragma unroll
        for (int o = 4; o; o >>= 1) {
            p0 += __shfl_xor_sync(0xffffffffu, p0, o);
            p1 += __shfl_xor_sync(0xffffffffu, p1, o);
            p2 += __shfl_xor_sync(0xffffffffu, p2, o);
        }
        if (q == 0) {
            snb[0 * 32 + node] = p0;
            snb[1 * 32 + node] = p1;
            snb[2 * 32 + node] = p2;
        }
    }

    // ---- s_self: 9 u-dots on node-0 row (warp-uniform loop shape) ----
    {
        float4 x0[4];
        #pragma unroll
        for (int k = 0; k < 4; ++k)
            x0[k] = ((const float4*)hb)[q + (k << 3)];   // node-0 row
        #pragma unroll
        for (int t = 0; t < 3; ++t) {
            int ui = g * 3 + t; if (ui > 8) ui = 8;      // groups 2/3 dup ui=8 (benign)
            const float* uvec = suu + ui * DIN;
            float p = 0.f;
            #pragma unroll
            for (int k = 0; k < 4; ++k)
                p += dot4(x0[k], *(const float4*)&uvec[(q + (k << 3)) << 2]);
            #pragma unroll
            for (int o = 4; o; o >>= 1) p += __shfl_xor_sync(0xffffffffu, p, o);
            if (q == 0) sss[ui] = p;
        }
    }
    __syncwarp();

    // ---- dual register-resident softmax (lanes 1..15 ally, 16..31 opp) ----
    const float r0 = snb[0 * 32 + lane];
    const float r1 = snb[1 * 32 + lane];
    const float r2 = snb[2 * 32 + lane];
    float ss[9];
    #pragma unroll
    for (int k = 0; k < 9; ++k) ss[k] = sss[k];

    const float eb0 = (m0 || lane == 0) ? -INFINITY : r0;
    const float eb1 = (m1 || lane == 0) ? -INFINITY : r1;
    const float eb2 = (m2 || lane == 0) ? -INFINITY : r2;

    float mx = -INFINITY;
    #pragma unroll
    for (int i = 0; i < 3; ++i) {
        mx = fmaxf(mx, ss[i * 3 + 0] + eb0);
        mx = fmaxf(mx, ss[i * 3 + 1] + eb1);
        mx = fmaxf(mx, ss[i * 3 + 2] + eb2);
    }
    #pragma unroll
    for (int o = 8; o; o >>= 1) mx = fmaxf(mx, __shfl_xor_sync(0xffffffffu, mx, o));

    float s0 = 0.f, s1 = 0.f, s2 = 0.f;
    #pragma unroll
    for (int i = 0; i < 3; ++i) {
        s0 += __expf(ss[i * 3 + 0] + eb0 - mx);
        s1 += __expf(ss[i * 3 + 1] + eb1 - mx);
        s2 += __expf(ss[i * 3 + 2] + eb2 - mx);
    }
    float zs = s0 + s1 + s2;
    #pragma unroll
    for (int o = 8; o; o >>= 1) zs += __shfl_xor_sync(0xffffffffu, zs, o);
    // all-masked half -> zs NaN -> inv 0 -> weights 0 (matches reference)
    const float inv = (zs > 0.f) ? (1.f / zs) : 0.f;

    swt[0 * 32 + lane] = (lane == 0) ? (m0 ? 1.f : 0.f) : s0 * inv;
    swt[1 * 32 + lane] = (lane == 0) ? (m1 ? 1.f : 0.f) : s1 * inv;
    swt[2 * 32 + lane] = (lane == 0) ? (m2 ? 1.f : 0.f) : s2 * inv;
    __syncwarp();

    // ---- combine: re-read h (L1/L2 hot), write c into smem A[w][.] ----
    {
        const float4* hv = (const float4*)hb;
        float4 a0 = {0.f, 0.f, 0.f, 0.f}, a1 = a0, a2 = a0;
        #pragma unroll
        for (int n = 0; n < NNODES; ++n) {
            float4 x = hv[(n << 5) + lane];
            float w0 = swt[n], w1 = swt[32 + n], w2 = swt[64 + n];
            a0.x += w0 * x.x; a0.y += w0 * x.y; a0.z += w0 * x.z; a0.w += w0 * x.w;
            a1.x += w1 * x.x; a1.y += w1 * x.y; a1.z += w1 * x.z; a1.w += w1 * x.w;
            a2.x += w2 * x.x; a2.y += w2 * x.y; a2.z += w2 * x.z; a2.w += w2 * x.w;
        }
        const int d4 = lane << 2;
        *(float4*)&Amat[w][0 * DIN + d4] = a0;
        *(float4*)&Amat[w][1 * DIN + d4] = a1;
        *(float4*)&Amat[w][2 * DIN + d4] = a2;
    }
    __syncthreads();

    // ---- mini-GEMM: out[b][d] = sum_k A[b][k] * Wstack[k][d] ----
    // warp = (bg = w&1: 4 batches) x (kg = w>>1: 96 k-values).
    // Lane owns d-quad; each 16B W-load feeds 4 batches (8 FMA2).
    {
        const int bg = w & 1;
        const int kg = w >> 1;
        const int d0 = lane << 2;
        const int kbase = kg * 96;

        unsigned long long acc[4][2];
        #pragma unroll
        for (int bi = 0; bi < 4; ++bi) { acc[bi][0] = 0ull; acc[bi][1] = 0ull; }

        const float* arow0 = &Amat[bg * 4 + 0][kbase];
        const float* arow1 = &Amat[bg * 4 + 1][kbase];
        const float* arow2 = &Amat[bg * 4 + 2][kbase];
        const float* arow3 = &Amat[bg * 4 + 3][kbase];

        #pragma unroll 4
        for (int kk = 0; kk < 96; ++kk) {
            ulonglong2 wrow = *(const ulonglong2*)&W[(size_t)(kbase + kk) * DIN + d0];
            unsigned long long ad;
            PACK_DUP(ad, __float_as_uint(arow0[kk]));
            FMA_F32X2(acc[0][0], ad, wrow.x, acc[0][0]);
            FMA_F32X2(acc[0][1], ad, wrow.y, acc[0][1]);
            PACK_DUP(ad, __float_as_uint(arow1[kk]));
            FMA_F32X2(acc[1][0], ad, wrow.x, acc[1][0]);
            FMA_F32X2(acc[1][1], ad, wrow.y, acc[1][1]);
            PACK_DUP(ad, __float_as_uint(arow2[kk]));
            FMA_F32X2(acc[2][0], ad, wrow.x, acc[2][0]);
            FMA_F32X2(acc[2][1], ad, wrow.y, acc[2][1]);
            PACK_DUP(ad, __float_as_uint(arow3[kk]));
            FMA_F32X2(acc[3][0], ad, wrow.x, acc[3][0]);
            FMA_F32X2(acc[3][1], ad, wrow.y, acc[3][1]);
        }

        #pragma unroll
        for (int bi = 0; bi < 4; ++bi) {
            float4 pv;
            pv.x = __uint_as_float((unsigned)(acc[bi][0] & 0xffffffffull));
            pv.y = __uint_as_float((unsigned)(acc[bi][0] >> 32));
            pv.z = __uint_as_float((unsigned)(acc[bi][1] & 0xffffffffull));
            pv.w = __uint_as_float((unsigned)(acc[bi][1] >> 32));
            *(float4*)&Pmat[kg][bg * 4 + bi][d0] = pv;
        }
    }
    __syncthreads();

    // ---- reduce 4 k-group partials, ELU, store ----
    {
        const int tid = threadIdx.x;
        const int bl  = tid >> 5;            // batch-local 0..7
        const int d0  = (tid & 31) << 2;
        float4 p0 = *(const float4*)&Pmat[0][bl][d0];
        float4 p1 = *(const float4*)&Pmat[1][bl][d0];
        float4 p2 = *(const float4*)&Pmat[2][bl][d0];
        float4 p3 = *(const float4*)&Pmat[3][bl][d0];
        float o4[4];
        o4[0] = (p0.x + p1.x) + (p2.x + p3.x);
        o4[1] = (p0.y + p1.y) + (p2.y + p3.y);
        o4[2] = (p0.z + p1.z) + (p2.z + p3.z);
        o4[3] = (p0.w + p1.w) + (p2.w + p3.w);
        #pragma unroll
        for (int qq = 0; qq < 4; ++qq) {
            float x = o4[qq];
            o4[qq] = x > 0.f ? x : expm1f(x);
        }
        const size_t ob = (size_t)(blockIdx.x * K1_WARPS + bl) * DIN + d0;
        *(float4*)&out[ob] = *(float4*)&o4[0];
    }
}

// ---------------------------------------------------------------------------
extern "C" void kernel_launch(void* const* d_in, const int* in_sizes, int n_in,
                              void* d_out, int out_size)
{
    const float* h = nullptr;
    const void*  mask = nullptr;
    const float* W = nullptr;
    const float* a = nullptr;

    for (int i = 0; i < n_in; ++i) {
        switch (in_sizes[i]) {
            case BATCH * NNODES * DIN: h    = (const float*)d_in[i]; break;   // 33554432
            case TT * BATCH * NNODES:  mask = d_in[i];               break;   // 786432
            case TT * DIN * HID:       W    = (const float*)d_in[i]; break;   // 49152
            case TT * 2 * HID:         a    = (const float*)d_in[i]; break;   // 768
            default: break; // scalars
        }
    }

    k0_precompute<<<25, 256>>>(W, a, (const unsigned*)mask);
    k1_fused<<<BATCH / K1_WARPS, 32 * K1_WARPS>>>(h, mask, W, (float*)d_out);
}